// round 2
// baseline (speedup 1.0000x reference)
#include <cuda_runtime.h>

#define NSAMP 65536
#define EPSF 1e-8f

// Shared layout: sM[(k*20 + c)*32 + lane]
//   c = 0..15 : M row-major (M = scale * L(qn), left Hamilton matrix)
//   c = 16..18: trans (t1,t2,t3); t0 = 0 implicit
// Lane l owns pairs p = 8*l + k  <=>  (o = l>>1, i = (l&1)*8 + k)

__global__ void __launch_bounds__(256)
caps_quat_kernel(const float* __restrict__ x,
                 const float* __restrict__ quats,
                 const float* __restrict__ scale,
                 const float* __restrict__ trans,
                 const float* __restrict__ bias,
                 const float* __restrict__ beta,
                 const float* __restrict__ alpha,
                 float* __restrict__ out)
{
    __shared__ float sM[8 * 20 * 32];

    const int tid = threadIdx.x;

    // ---- per-block precompute of M,t into shared (conflict-free writes) ----
    {
        const int lane_p = tid & 31;       // lane that will read this slot
        const int k_p    = tid >> 5;       // k-step
        const int o_p    = lane_p >> 1;
        const int i_p    = ((lane_p & 1) << 3) | k_p;
        const int pi     = o_p * 16 + i_p;

        float qw = quats[pi * 4 + 0];
        float qx = quats[pi * 4 + 1];
        float qy = quats[pi * 4 + 2];
        float qz = quats[pi * 4 + 3];
        const float inv = rsqrtf(fmaf(qw, qw, fmaf(qx, qx, fmaf(qy, qy, qz * qz))) + EPSF);
        const float f   = inv * scale[pi];
        qw *= f; qx *= f; qy *= f; qz *= f;

        float* m = &sM[(k_p * 20) * 32 + lane_p];
        // row0:  w -x -y -z
        m[0 * 32] = qw;   m[1 * 32] = -qx;  m[2 * 32]  = -qy;  m[3 * 32]  = -qz;
        // row1:  x  w -z  y
        m[4 * 32] = qx;   m[5 * 32] = qw;   m[6 * 32]  = -qz;  m[7 * 32]  = qy;
        // row2:  y  z  w -x
        m[8 * 32] = qy;   m[9 * 32] = qz;   m[10 * 32] = qw;   m[11 * 32] = -qx;
        // row3:  z -y  x  w
        m[12 * 32] = qz;  m[13 * 32] = -qy; m[14 * 32] = qx;   m[15 * 32] = qw;
        m[16 * 32] = trans[pi * 3 + 0];
        m[17 * 32] = trans[pi * 3 + 1];
        m[18 * 32] = trans[pi * 3 + 2];
    }
    __syncthreads();

    const int lane = tid & 31;
    const int h    = lane & 1;       // i-half
    const int o    = lane >> 1;      // output capsule
    const int n    = blockIdx.x * 8 + (tid >> 5);   // sample (one warp per sample)

    // ---- votes: 8 per lane, register-resident ----
    const float4* __restrict__ x4 = (const float4*)x;
    float vw[8], vx[8], vy[8], vz[8];
#pragma unroll
    for (int k = 0; k < 8; k++) {
        const float4 xq = __ldg(&x4[n * 16 + h * 8 + k]);
        const float* m = &sM[(k * 20) * 32 + lane];
        vw[k] = fmaf(m[0 * 32],  xq.x, fmaf(m[1 * 32],  xq.y, fmaf(m[2 * 32],  xq.z, m[3 * 32] * xq.w)));
        vx[k] = fmaf(m[4 * 32],  xq.x, fmaf(m[5 * 32],  xq.y, fmaf(m[6 * 32],  xq.z, fmaf(m[7 * 32],  xq.w, m[16 * 32]))));
        vy[k] = fmaf(m[8 * 32],  xq.x, fmaf(m[9 * 32],  xq.y, fmaf(m[10 * 32], xq.z, fmaf(m[11 * 32], xq.w, m[17 * 32]))));
        vz[k] = fmaf(m[12 * 32], xq.x, fmaf(m[13 * 32], xq.y, fmaf(m[14 * 32], xq.z, fmaf(m[15 * 32], xq.w, m[18 * 32]))));
    }

    // ---- dynamic routing, 3 iterations ----
    float bb[8];
#pragma unroll
    for (int k = 0; k < 8; k++) bb[k] = 0.0f;

    float s0 = 0.f, s1 = 0.f, s2 = 0.f, s3 = 0.f;
    float v0 = 0.f, v1 = 0.f, v2 = 0.f, v3 = 0.f;
    float n2 = 0.f;

#pragma unroll
    for (int iter = 0; iter < 3; iter++) {
        float c[8];
        if (iter == 0) {
            // b == 0 -> softmax over 16 output caps is uniform
#pragma unroll
            for (int k = 0; k < 8; k++) c[k] = 0.0625f;
        } else {
            // max-subtracted softmax over o (xor masks 2,4,8,16 sweep the o bits)
            float mx[8], e[8], den[8];
#pragma unroll
            for (int k = 0; k < 8; k++) mx[k] = bb[k];
#pragma unroll
            for (int msk = 2; msk <= 16; msk <<= 1) {
#pragma unroll
                for (int k = 0; k < 8; k++)
                    mx[k] = fmaxf(mx[k], __shfl_xor_sync(0xffffffffu, mx[k], msk));
            }
#pragma unroll
            for (int k = 0; k < 8; k++) { e[k] = __expf(bb[k] - mx[k]); den[k] = e[k]; }
#pragma unroll
            for (int msk = 2; msk <= 16; msk <<= 1) {
#pragma unroll
                for (int k = 0; k < 8; k++)
                    den[k] += __shfl_xor_sync(0xffffffffu, den[k], msk);
            }
#pragma unroll
            for (int k = 0; k < 8; k++) c[k] = __fdividef(e[k], den[k]);
        }

        // s[o,d] = sum_i c[o,i] * votes[o,i,d]  (partial over 8 i's, then xor-1)
        s0 = s1 = s2 = s3 = 0.f;
#pragma unroll
        for (int k = 0; k < 8; k++) {
            s0 = fmaf(c[k], vw[k], s0);
            s1 = fmaf(c[k], vx[k], s1);
            s2 = fmaf(c[k], vy[k], s2);
            s3 = fmaf(c[k], vz[k], s3);
        }
        s0 += __shfl_xor_sync(0xffffffffu, s0, 1);
        s1 += __shfl_xor_sync(0xffffffffu, s1, 1);
        s2 += __shfl_xor_sync(0xffffffffu, s2, 1);
        s3 += __shfl_xor_sync(0xffffffffu, s3, 1);

        // squash
        n2 = fmaf(s0, s0, fmaf(s1, s1, fmaf(s2, s2, s3 * s3)));
        const float fac = __fdividef(n2, 1.0f + n2) * rsqrtf(n2 + EPSF);
        v0 = s0 * fac; v1 = s1 * fac; v2 = s2 * fac; v3 = s3 * fac;

        // agreement update (dead on the last iteration)
        if (iter < 2) {
#pragma unroll
            for (int k = 0; k < 8; k++)
                bb[k] = fmaf(v0, vw[k], fmaf(v1, vx[k], fmaf(v2, vy[k], fmaf(v3, vz[k], bb[k]))));
        }
    }

    // ---- activation + store ----
    const float norm_s = sqrtf(n2 + EPSF);
    const float z = fmaf(__ldg(&beta[o]), norm_s, __ldg(&alpha[o]) + __ldg(&bias[o]));
    const float a = __fdividef(1.0f, 1.0f + __expf(-z));

    if (h == 0) {
        ((float4*)out)[n * 16 + o] = make_float4(v0 * a, v1 * a, v2 * a, v3 * a);
    }
}

extern "C" void kernel_launch(void* const* d_in, const int* in_sizes, int n_in,
                              void* d_out, int out_size)
{
    const float* x     = (const float*)d_in[0];
    const float* quats = (const float*)d_in[1];
    const float* scale = (const float*)d_in[2];
    const float* trans = (const float*)d_in[3];
    const float* bias  = (const float*)d_in[4];
    const float* beta  = (const float*)d_in[5];
    const float* alpha = (const float*)d_in[6];

    caps_quat_kernel<<<NSAMP / 8, 256>>>(x, quats, scale, trans, bias, beta, alpha,
                                         (float*)d_out);
}

// round 3
// speedup vs baseline: 1.9878x; 1.9878x over previous
#include <cuda_runtime.h>

#define NSAMP 65536
#define EPSF 1e-8f
#define TOTAL_WARPS 4096
#define BLOCK_THREADS 128
#define NBLOCKS (TOTAL_WARPS / (BLOCK_THREADS / 32))

// Warp-per-sample, register-resident persistent kernel.
// Lane l -> (o = l>>1, i-half h = l&1); lane owns pairs (o, i = h*8+k), k=0..7.
// Scaled quaternion + translation (7 floats x 8 pairs = 56 regs) live in
// registers for the whole kernel; each warp loops over NSAMP/TOTAL_WARPS samples.

__global__ void __launch_bounds__(BLOCK_THREADS)
caps_quat_kernel(const float* __restrict__ x,
                 const float* __restrict__ quats,
                 const float* __restrict__ scale,
                 const float* __restrict__ trans,
                 const float* __restrict__ bias,
                 const float* __restrict__ beta,
                 const float* __restrict__ alpha,
                 float* __restrict__ out)
{
    const int lane = threadIdx.x & 31;
    const int warp = blockIdx.x * (BLOCK_THREADS / 32) + (threadIdx.x >> 5);
    const int h    = lane & 1;       // i-half
    const int o    = lane >> 1;      // output capsule

    // ---- one-time prologue: scaled quaternion + trans for this lane's 8 pairs ----
    float qw[8], qx[8], qy[8], qz[8], t1[8], t2[8], t3[8];
    const float4* __restrict__ q4 = (const float4*)quats;
#pragma unroll
    for (int k = 0; k < 8; k++) {
        const int pi = o * 16 + h * 8 + k;
        const float4 q = __ldg(&q4[pi]);
        const float f = rsqrtf(fmaf(q.x, q.x, fmaf(q.y, q.y, fmaf(q.z, q.z, q.w * q.w))) + EPSF)
                        * __ldg(&scale[pi]);
        qw[k] = q.x * f; qx[k] = q.y * f; qy[k] = q.z * f; qz[k] = q.w * f;
        t1[k] = __ldg(&trans[pi * 3 + 0]);
        t2[k] = __ldg(&trans[pi * 3 + 1]);
        t3[k] = __ldg(&trans[pi * 3 + 2]);
    }
    const float bet = __ldg(&beta[o]);
    const float ab  = __ldg(&alpha[o]) + __ldg(&bias[o]);

    const float4* __restrict__ x4   = (const float4*)x;
    float4* __restrict__       out4 = (float4*)out;

    for (int n = warp; n < NSAMP; n += TOTAL_WARPS) {
        // ---- votes: Hamilton product directly from quaternion registers ----
        float vw[8], vx[8], vy[8], vz[8];
#pragma unroll
        for (int k = 0; k < 8; k++) {
            const float4 X = __ldg(&x4[n * 16 + h * 8 + k]);
            vw[k] = fmaf(qw[k], X.x, fmaf(-qx[k], X.y, fmaf(-qy[k], X.z, -qz[k] * X.w)));
            vx[k] = fmaf(qw[k], X.y, fmaf( qx[k], X.x, fmaf( qy[k], X.w, fmaf(-qz[k], X.z, t1[k]))));
            vy[k] = fmaf(qw[k], X.z, fmaf(-qx[k], X.w, fmaf( qy[k], X.x, fmaf( qz[k], X.y, t2[k]))));
            vz[k] = fmaf(qw[k], X.w, fmaf( qx[k], X.z, fmaf(-qy[k], X.y, fmaf( qz[k], X.x, t3[k]))));
        }

        // ---- dynamic routing, 3 iterations ----
        float bb[8];
#pragma unroll
        for (int k = 0; k < 8; k++) bb[k] = 0.0f;

        float s0, s1, s2, s3, v0, v1, v2, v3, n2 = 0.0f;

#pragma unroll
        for (int iter = 0; iter < 3; iter++) {
            if (iter == 0) {
                // b == 0 -> uniform coupling c = 1/16: plain sums scaled once
                s0 = vw[0]; s1 = vx[0]; s2 = vy[0]; s3 = vz[0];
#pragma unroll
                for (int k = 1; k < 8; k++) {
                    s0 += vw[k]; s1 += vx[k]; s2 += vy[k]; s3 += vz[k];
                }
                s0 *= 0.0625f; s1 *= 0.0625f; s2 *= 0.0625f; s3 *= 0.0625f;
            } else {
                // softmax over o without max-subtraction (|b| small enough; no overflow)
                float e[8], den[8];
#pragma unroll
                for (int k = 0; k < 8; k++) { e[k] = __expf(bb[k]); den[k] = e[k]; }
#pragma unroll
                for (int msk = 2; msk <= 16; msk <<= 1) {
#pragma unroll
                    for (int k = 0; k < 8; k++)
                        den[k] += __shfl_xor_sync(0xffffffffu, den[k], msk);
                }
                float c[8];
#pragma unroll
                for (int k = 0; k < 8; k++) c[k] = __fdividef(e[k], den[k]);

                s0 = s1 = s2 = s3 = 0.0f;
#pragma unroll
                for (int k = 0; k < 8; k++) {
                    s0 = fmaf(c[k], vw[k], s0);
                    s1 = fmaf(c[k], vx[k], s1);
                    s2 = fmaf(c[k], vy[k], s2);
                    s3 = fmaf(c[k], vz[k], s3);
                }
            }
            // fold the two i-halves
            s0 += __shfl_xor_sync(0xffffffffu, s0, 1);
            s1 += __shfl_xor_sync(0xffffffffu, s1, 1);
            s2 += __shfl_xor_sync(0xffffffffu, s2, 1);
            s3 += __shfl_xor_sync(0xffffffffu, s3, 1);

            // squash
            n2 = fmaf(s0, s0, fmaf(s1, s1, fmaf(s2, s2, s3 * s3)));
            const float fac = __fdividef(n2, 1.0f + n2) * rsqrtf(n2 + EPSF);
            v0 = s0 * fac; v1 = s1 * fac; v2 = s2 * fac; v3 = s3 * fac;

            // agreement update (dead on the last iteration)
            if (iter < 2) {
#pragma unroll
                for (int k = 0; k < 8; k++)
                    bb[k] = fmaf(v0, vw[k], fmaf(v1, vx[k], fmaf(v2, vy[k], fmaf(v3, vz[k], bb[k]))));
            }
        }

        // ---- activation + store (even lanes: one coalesced float4 per (n,o)) ----
        const float norm_s = sqrtf(n2 + EPSF);
        const float z = fmaf(bet, norm_s, ab);
        const float a = __fdividef(1.0f, 1.0f + __expf(-z));

        if (h == 0) {
            out4[n * 16 + o] = make_float4(v0 * a, v1 * a, v2 * a, v3 * a);
        }
    }
}

extern "C" void kernel_launch(void* const* d_in, const int* in_sizes, int n_in,
                              void* d_out, int out_size)
{
    const float* x     = (const float*)d_in[0];
    const float* quats = (const float*)d_in[1];
    const float* scale = (const float*)d_in[2];
    const float* trans = (const float*)d_in[3];
    const float* bias  = (const float*)d_in[4];
    const float* beta  = (const float*)d_in[5];
    const float* alpha = (const float*)d_in[6];

    caps_quat_kernel<<<NBLOCKS, BLOCK_THREADS>>>(x, quats, scale, trans, bias, beta, alpha,
                                                 (float*)d_out);
}